// round 1
// baseline (speedup 1.0000x reference)
#include <cuda_runtime.h>
#include <math.h>

#define BB 2
#define TT 2048
#define DD 2048
#define NHEADS 16
#define NKVH 8
#define HDIM 128

// Scratch (allocation-free rule: __device__ globals)
static __device__ float g_q[(size_t)BB * NHEADS * TT * HDIM];   // [b][n][t][h]
static __device__ float g_kv[(size_t)BB * 16 * TT * HDIM];      // [b][j][t][h], j<8 = K head j, j>=8 = V head j-8
static __device__ float g_enc[(size_t)BB * TT * NHEADS * HDIM]; // [b][t][n*128+h]

// ---------------------------------------------------------------------------
// 128x128x8 SGEMM body, 256 threads, 8x8 microtile, split-quadrant mapping
// A row-major [M,K] (lda), B row-major [K,N] (ldb), C row-major (ldc)
// ---------------------------------------------------------------------------
__device__ __forceinline__ void gemm128_body(
    const float* __restrict__ A, int lda,
    const float* __restrict__ Bm, int ldb,
    float* __restrict__ C, int ldc,
    int K, int m0, int n0)
{
    __shared__ float As[8][128];
    __shared__ float Bs[8][128];
    const int tid = threadIdx.x;
    const int tx = tid & 15, ty = tid >> 4;
    const int la_m = tid & 127, la_k = (tid >> 7) << 2;
    const int lb_k = tid >> 5, lb_n = (tid & 31) << 2;

    float acc[8][8];
#pragma unroll
    for (int i = 0; i < 8; i++)
#pragma unroll
        for (int j = 0; j < 8; j++) acc[i][j] = 0.0f;

    const float* Aptr = A + (size_t)(m0 + la_m) * lda + la_k;
    const float* Bptr = Bm + (size_t)lb_k * ldb + n0 + lb_n;

    for (int k0 = 0; k0 < K; k0 += 8) {
        float4 av = *(const float4*)(Aptr + k0);
        float4 bv = *(const float4*)(Bptr + (size_t)k0 * ldb);
        __syncthreads();
        As[la_k + 0][la_m] = av.x;
        As[la_k + 1][la_m] = av.y;
        As[la_k + 2][la_m] = av.z;
        As[la_k + 3][la_m] = av.w;
        *(float4*)&Bs[lb_k][lb_n] = bv;
        __syncthreads();
#pragma unroll
        for (int kk = 0; kk < 8; kk++) {
            float a[8], bb[8];
            *(float4*)(a + 0) = *(const float4*)&As[kk][ty * 4];
            *(float4*)(a + 4) = *(const float4*)&As[kk][64 + ty * 4];
            *(float4*)(bb + 0) = *(const float4*)&Bs[kk][tx * 4];
            *(float4*)(bb + 4) = *(const float4*)&Bs[kk][64 + tx * 4];
#pragma unroll
            for (int i = 0; i < 8; i++)
#pragma unroll
                for (int j = 0; j < 8; j++)
                    acc[i][j] = fmaf(a[i], bb[j], acc[i][j]);
        }
    }
#pragma unroll
    for (int i = 0; i < 8; i++) {
        int r = m0 + ty * 4 + (i < 4 ? i : 64 + (i - 4));
        float* Crow = C + (size_t)r * ldc + n0;
        float4 v0 = make_float4(acc[i][0], acc[i][1], acc[i][2], acc[i][3]);
        float4 v1 = make_float4(acc[i][4], acc[i][5], acc[i][6], acc[i][7]);
        *(float4*)(Crow + tx * 4) = v0;
        *(float4*)(Crow + 64 + tx * 4) = v1;
    }
}

// Projection: per (b, head) GEMM [T,D] x [D,128] -> out[b][head][T][128]
__global__ __launch_bounds__(256) void proj_kernel(
    const float* __restrict__ x, const float* __restrict__ W,
    float* __restrict__ out, int nheads)
{
    const int bh = blockIdx.y;
    const int b = bh / nheads, h = bh % nheads;
    gemm128_body(x + (size_t)b * TT * DD, DD,
                 W + (size_t)h * DD * HDIM, HDIM,
                 out + (size_t)bh * TT * HDIM, HDIM,
                 DD, blockIdx.x * 128, 0);
}

// Out projection: enc[4096,2048] x w_out[2048,2048] -> out[4096,2048]
__global__ __launch_bounds__(256) void outproj_kernel(
    const float* __restrict__ w_out, float* __restrict__ out)
{
    gemm128_body(g_enc, NHEADS * HDIM, w_out, DD, out, DD,
                 NHEADS * HDIM, blockIdx.x * 128, blockIdx.y * 128);
}

// RoPE (double-precision angle path), optional scale fused (q * H^-0.5)
__global__ void rope_kernel(float* __restrict__ buf, const int* __restrict__ pos,
                            int nheads, int strideHeads, float scale)
{
    int idx = blockIdx.x * blockDim.x + threadIdx.x;
    int i = idx & 63;
    int t = (idx >> 6) & (TT - 1);
    int rest = idx >> 17; // 64*2048 = 1<<17
    int hd = rest % nheads;
    int b = rest / nheads;
    if (b >= BB) return;
    size_t base = (((size_t)(b * strideHeads + hd)) * TT + t) * HDIM;
    double p = (double)pos[b * TT + t];
    double ts = pow(10000.0, -(double)i / 64.0);
    double th = p * ts;
    double sd, cd;
    sincos(th, &sd, &cd);
    float s = (float)sd, c = (float)cd;
    float f = buf[base + i];
    float se = buf[base + 64 + i];
    buf[base + i] = (f * c - se * s) * scale;
    buf[base + 64 + i] = (se * c + f * s) * scale;
}

// ---------------------------------------------------------------------------
// Flash attention: 64 q-rows per block, stream 64-wide KV tiles (causal),
// tanh softcap, online softmax. 256 threads. Writes encoded [b][t][n*128+h].
// ---------------------------------------------------------------------------
#define PS_LD 65
#define SMEM_ATTN ((128 * 64 * 2 + 64 * 128 + 64 * PS_LD + 64 * 3) * 4)

__global__ __launch_bounds__(256) void attn_kernel()
{
    extern __shared__ float sm[];
    float* Qt = sm;              // [128][64] (K-major transposed)
    float* Kt = Qt + 128 * 64;   // [128][64]
    float* Vs = Kt + 128 * 64;   // [64][128]
    float* Ps = Vs + 64 * 128;   // [64][PS_LD]
    float* mrow = Ps + 64 * PS_LD;
    float* lrow = mrow + 64;
    float* arow = lrow + 64;

    const int tid = threadIdx.x;
    const int tx = tid & 15, ty = tid >> 4;
    const int q0 = blockIdx.x * 64;
    const int n = blockIdx.y, b = blockIdx.z;
    const int kvh = n >> 1; // G = NHEADS / NKVH = 2
    const float* Qp = g_q + ((size_t)(b * NHEADS + n)) * TT * HDIM;
    const float* Kp = g_kv + ((size_t)(b * 16 + kvh)) * TT * HDIM;
    const float* Vp = g_kv + ((size_t)(b * 16 + 8 + kvh)) * TT * HDIM;

    // load Q tile transposed
    {
        int c = tid & 63, k4 = (tid >> 6) << 2;
#pragma unroll
        for (int kb = 0; kb < 8; kb++) {
            int k = kb * 16 + k4;
            float4 v = *(const float4*)(Qp + (size_t)(q0 + c) * HDIM + k);
            Qt[(k + 0) * 64 + c] = v.x;
            Qt[(k + 1) * 64 + c] = v.y;
            Qt[(k + 2) * 64 + c] = v.z;
            Qt[(k + 3) * 64 + c] = v.w;
        }
    }
    if (tid < 64) { mrow[tid] = -3.0e38f; lrow[tid] = 0.0f; }

    float o[4][8];
#pragma unroll
    for (int i = 0; i < 4; i++)
#pragma unroll
        for (int j = 0; j < 8; j++) o[i][j] = 0.0f;

    const int ntiles = blockIdx.x + 1;
    for (int tile = 0; tile < ntiles; tile++) {
        const int s0 = tile * 64;
        __syncthreads(); // prev PV / Q load done before overwriting Kt,Vs
        {
            int c = tid & 63, k4 = (tid >> 6) << 2;
#pragma unroll
            for (int kb = 0; kb < 8; kb++) {
                int k = kb * 16 + k4;
                float4 v = *(const float4*)(Kp + (size_t)(s0 + c) * HDIM + k);
                Kt[(k + 0) * 64 + c] = v.x;
                Kt[(k + 1) * 64 + c] = v.y;
                Kt[(k + 2) * 64 + c] = v.z;
                Kt[(k + 3) * 64 + c] = v.w;
            }
#pragma unroll
            for (int it = 0; it < 8; it++) {
                int idx4 = tid + it * 256;
                int s = idx4 >> 5, c4 = (idx4 & 31) << 2;
                *(float4*)(Vs + s * 128 + c4) =
                    *(const float4*)(Vp + (size_t)(s0 + s) * HDIM + c4);
            }
        }
        __syncthreads();

        // S = Q K^T (64x64), 4x4 per thread
        float sa[4][4];
#pragma unroll
        for (int i = 0; i < 4; i++)
#pragma unroll
            for (int j = 0; j < 4; j++) sa[i][j] = 0.0f;
#pragma unroll 8
        for (int k = 0; k < 128; k++) {
            float4 a4 = *(const float4*)(Qt + k * 64 + ty * 4);
            float4 b4 = *(const float4*)(Kt + k * 64 + tx * 4);
            const float av[4] = {a4.x, a4.y, a4.z, a4.w};
            const float bv[4] = {b4.x, b4.y, b4.z, b4.w};
#pragma unroll
            for (int i = 0; i < 4; i++)
#pragma unroll
                for (int j = 0; j < 4; j++)
                    sa[i][j] = fmaf(av[i], bv[j], sa[i][j]);
        }

        // softcap + causal mask, stash to Ps for row stats
#pragma unroll
        for (int i = 0; i < 4; i++) {
            int tq = q0 + ty * 4 + i;
#pragma unroll
            for (int j = 0; j < 4; j++) {
                float v = 50.0f * tanhf(sa[i][j] * 0.02f);
                if (s0 + tx * 4 + j > tq) v = -2.3819763e38f;
                sa[i][j] = v;
                Ps[(ty * 4 + i) * PS_LD + tx * 4 + j] = v;
            }
        }
        __syncthreads();
        if (tid < 64) {
            float mo = mrow[tid], mx = mo;
#pragma unroll 8
            for (int s = 0; s < 64; s++) mx = fmaxf(mx, Ps[tid * PS_LD + s]);
            mrow[tid] = mx;
            arow[tid] = __expf(mo - mx);
        }
        __syncthreads();
        // exponentiate + rescale O accumulators
#pragma unroll
        for (int i = 0; i < 4; i++) {
            float mr = mrow[ty * 4 + i];
            float al = arow[ty * 4 + i];
#pragma unroll
            for (int j = 0; j < 4; j++) {
                float p = __expf(sa[i][j] - mr);
                Ps[(ty * 4 + i) * PS_LD + tx * 4 + j] = p;
            }
#pragma unroll
            for (int j = 0; j < 8; j++) o[i][j] *= al;
        }
        __syncthreads();
        if (tid < 64) {
            float sum = 0.0f;
#pragma unroll 8
            for (int s = 0; s < 64; s++) sum += Ps[tid * PS_LD + s];
            lrow[tid] = lrow[tid] * arow[tid] + sum;
        }
        // O += P V (cols tx + 16*j: broadcast-friendly)
#pragma unroll 4
        for (int s = 0; s < 64; s++) {
            float p0 = Ps[(ty * 4 + 0) * PS_LD + s];
            float p1 = Ps[(ty * 4 + 1) * PS_LD + s];
            float p2 = Ps[(ty * 4 + 2) * PS_LD + s];
            float p3 = Ps[(ty * 4 + 3) * PS_LD + s];
#pragma unroll
            for (int j = 0; j < 8; j++) {
                float vv = Vs[s * 128 + tx + 16 * j];
                o[0][j] = fmaf(p0, vv, o[0][j]);
                o[1][j] = fmaf(p1, vv, o[1][j]);
                o[2][j] = fmaf(p2, vv, o[2][j]);
                o[3][j] = fmaf(p3, vv, o[3][j]);
            }
        }
    }
    __syncthreads();
#pragma unroll
    for (int i = 0; i < 4; i++) {
        float inv = 1.0f / lrow[ty * 4 + i];
        size_t rowb = ((size_t)b * TT + q0 + ty * 4 + i) * (NHEADS * HDIM) + n * HDIM;
#pragma unroll
        for (int j = 0; j < 8; j++)
            g_enc[rowb + tx + 16 * j] = o[i][j] * inv;
    }
}

// ---------------------------------------------------------------------------
extern "C" void kernel_launch(void* const* d_in, const int* in_sizes, int n_in,
                              void* d_out, int out_size)
{
    const float* x = (const float*)d_in[0];
    const int* positions = (const int*)d_in[1];
    // d_in[2] = attn_mask (causal tril) — implemented analytically
    const float* w_q = (const float*)d_in[3];
    const float* w_kv = (const float*)d_in[4];
    const float* w_out = (const float*)d_in[5];
    float* out = (float*)d_out;

    float *qb = nullptr, *kvb = nullptr;
    cudaGetSymbolAddress((void**)&qb, g_q);
    cudaGetSymbolAddress((void**)&kvb, g_kv);

    // 1) projections: Q (16 heads), KV (16 "heads" = [2,8] flattened)
    proj_kernel<<<dim3(TT / 128, BB * NHEADS), 256>>>(x, w_q, qb, NHEADS);
    proj_kernel<<<dim3(TT / 128, BB * 16), 256>>>(x, w_kv, kvb, 16);

    // 2) RoPE: q (scaled by H^-0.5), k (heads 0..7 of kv buffer)
    rope_kernel<<<(BB * NHEADS * TT * 64) / 256, 256>>>(
        qb, positions, NHEADS, NHEADS, 0.08838834764831845f);
    rope_kernel<<<(BB * NKVH * TT * 64) / 256, 256>>>(
        kvb, positions, NKVH, 16, 1.0f);

    // 3) flash attention
    cudaFuncSetAttribute(attn_kernel, cudaFuncAttributeMaxDynamicSharedMemorySize,
                         SMEM_ATTN);
    attn_kernel<<<dim3(TT / 64, NHEADS, BB), 256, SMEM_ATTN>>>();

    // 4) output projection
    outproj_kernel<<<dim3((BB * TT) / 128, DD / 128), 256>>>(w_out, out);
}

// round 2
// speedup vs baseline: 2.2723x; 2.2723x over previous
#include <cuda_runtime.h>
#include <math.h>
#include <stdint.h>

#define BB 2
#define TT 2048
#define DD 2048
#define NHEADS 16
#define NKVH 8
#define HDIM 128

// Scratch (allocation-free rule: __device__ globals)
static __device__ float g_q[(size_t)BB * NHEADS * TT * HDIM];   // [b][n][t][h]
static __device__ float g_kv[(size_t)BB * 16 * TT * HDIM];      // [b][j][t][h], j<8=K, j>=8=V
static __device__ float g_enc[(size_t)BB * TT * NHEADS * HDIM]; // [b][t][n*128+h]
static __device__ float2 g_tab[(size_t)BB * TT * 64];           // rope cos/sin

// ---------------------------------------------------------------------------
// tf32 helpers
// ---------------------------------------------------------------------------
__device__ __forceinline__ float tf32r(float x) {
    uint32_t u;
    asm("cvt.rna.tf32.f32 %0, %1;" : "=r"(u) : "f"(x));
    return __uint_as_float(u);
}
__device__ __forceinline__ uint32_t smem_u32(const void* p) {
    return (uint32_t)__cvta_generic_to_shared(p);
}
__device__ __forceinline__ void ldm4(uint32_t* r, uint32_t addr) {
    asm volatile("ldmatrix.sync.aligned.m8n8.x4.shared.b16 {%0,%1,%2,%3}, [%4];"
                 : "=r"(r[0]), "=r"(r[1]), "=r"(r[2]), "=r"(r[3]) : "r"(addr));
}
__device__ __forceinline__ void mma_tf32(float* d, const uint32_t* a, const uint32_t* b) {
    asm volatile(
        "mma.sync.aligned.m16n8k8.row.col.f32.tf32.tf32.f32 "
        "{%0,%1,%2,%3}, {%4,%5,%6,%7}, {%8,%9}, {%0,%1,%2,%3};"
        : "+f"(d[0]), "+f"(d[1]), "+f"(d[2]), "+f"(d[3])
        : "r"(a[0]), "r"(a[1]), "r"(a[2]), "r"(a[3]), "r"(b[0]), "r"(b[1]));
}

// ---------------------------------------------------------------------------
// tf32 GEMM body: 128x128 tile, BK=32, 256 threads (8 warps, 4x2 grid),
// warp tile 32x64 via m16n8k8 mma. A row-major [M,K], B row-major [K,N].
// ---------------------------------------------------------------------------
#define ALD 36   // As row stride (floats): ldmatrix conflict-free
#define BLD 136  // Bs row stride (floats): LDS frag conflict-free

__device__ __forceinline__ void gemm_tf32_body(
    const float* __restrict__ A, int lda,
    const float* __restrict__ B, int ldb,
    float* __restrict__ C, int ldc,
    int K, int m0, int n0)
{
    __shared__ float As[128 * ALD];  // [m][k]
    __shared__ float Bs[32 * BLD];   // [k][n]
    const int tid = threadIdx.x;
    const int lane = tid & 31, warp = tid >> 5;
    const int m_warp = (warp & 3) * 32, n_warp = (warp >> 2) * 64;

    // loader offsets (A: 4 float4 along k; B: 4 float4 along n)
    int aoff[4], asm_[4], boff[4], bsm_[4];
#pragma unroll
    for (int i = 0; i < 4; i++) {
        int idx = tid + i * 256;
        int m = idx >> 3, k4 = (idx & 7) * 4;
        aoff[i] = (m0 + m) * lda + k4;
        asm_[i] = m * ALD + k4;
        int kb = idx >> 5, n4 = (idx & 31) * 4;
        boff[i] = kb * ldb + n0 + n4;
        bsm_[i] = kb * BLD + n4;
    }

    // ldmatrix addresses for A frags
    uint32_t aAddr[2];
    {
        uint32_t baseA = smem_u32(As);
        int r = lane & 15;
        int cA = (lane & 16) ? 4 : 0;
#pragma unroll
        for (int mt = 0; mt < 2; mt++)
            aAddr[mt] = baseA + (uint32_t)((m_warp + mt * 16 + r) * ALD + cA) * 4u;
    }
    // B frag smem indices (LDS.32): b0 at [k8+(l&3)][n], b1 at [k8+4+(l&3)][n]
    const int bk = lane & 3, bn = n_warp + (lane >> 2);

    float acc[2][8][4];
#pragma unroll
    for (int mt = 0; mt < 2; mt++)
#pragma unroll
        for (int nt = 0; nt < 8; nt++)
#pragma unroll
            for (int e = 0; e < 4; e++) acc[mt][nt][e] = 0.0f;

    float4 ra[4], rb[4];
#pragma unroll
    for (int i = 0; i < 4; i++) {
        ra[i] = *(const float4*)(A + aoff[i]);
        rb[i] = *(const float4*)(B + boff[i]);
    }

    for (int k0 = 0; k0 < K; k0 += 32) {
        __syncthreads();
#pragma unroll
        for (int i = 0; i < 4; i++) {
            float4 v = ra[i];
            v.x = tf32r(v.x); v.y = tf32r(v.y); v.z = tf32r(v.z); v.w = tf32r(v.w);
            *(float4*)&As[asm_[i]] = v;
            float4 w = rb[i];
            w.x = tf32r(w.x); w.y = tf32r(w.y); w.z = tf32r(w.z); w.w = tf32r(w.w);
            *(float4*)&Bs[bsm_[i]] = w;
        }
        __syncthreads();
        if (k0 + 32 < K) {
#pragma unroll
            for (int i = 0; i < 4; i++) {
                ra[i] = *(const float4*)(A + aoff[i] + k0 + 32);
                rb[i] = *(const float4*)(B + boff[i] + (k0 + 32) * ldb);
            }
        }
#pragma unroll
        for (int k8 = 0; k8 < 4; k8++) {
            uint32_t af[2][4];
#pragma unroll
            for (int mt = 0; mt < 2; mt++) ldm4(af[mt], aAddr[mt] + (uint32_t)k8 * 32u);
            uint32_t bf[8][2];
#pragma unroll
            for (int nt = 0; nt < 8; nt++) {
                bf[nt][0] = __float_as_uint(Bs[(k8 * 8 + bk) * BLD + bn + nt * 8]);
                bf[nt][1] = __float_as_uint(Bs[(k8 * 8 + 4 + bk) * BLD + bn + nt * 8]);
            }
#pragma unroll
            for (int mt = 0; mt < 2; mt++)
#pragma unroll
                for (int nt = 0; nt < 8; nt++)
                    mma_tf32(acc[mt][nt], af[mt], bf[nt]);
        }
    }

    // epilogue: C frag -> gmem (STG.64)
    const int r = lane >> 2, cq = (lane & 3) * 2;
#pragma unroll
    for (int mt = 0; mt < 2; mt++) {
        int row = m0 + m_warp + mt * 16 + r;
#pragma unroll
        for (int nt = 0; nt < 8; nt++) {
            int col = n0 + n_warp + nt * 8 + cq;
            *(float2*)&C[(size_t)row * ldc + col] = make_float2(acc[mt][nt][0], acc[mt][nt][1]);
            *(float2*)&C[(size_t)(row + 8) * ldc + col] = make_float2(acc[mt][nt][2], acc[mt][nt][3]);
        }
    }
}

__global__ __launch_bounds__(256) void proj_tf32(
    const float* __restrict__ x, const float* __restrict__ W,
    float* __restrict__ out, int nheads)
{
    const int bh = blockIdx.y;
    const int b = bh / nheads, h = bh % nheads;
    gemm_tf32_body(x + (size_t)b * TT * DD, DD,
                   W + (size_t)h * DD * HDIM, HDIM,
                   out + (size_t)bh * TT * HDIM, HDIM,
                   DD, blockIdx.x * 128, 0);
}

__global__ __launch_bounds__(256) void outproj_tf32(
    const float* __restrict__ w_out, float* __restrict__ out)
{
    gemm_tf32_body(g_enc, NHEADS * HDIM, w_out, DD, out, DD,
                   NHEADS * HDIM, blockIdx.x * 128, blockIdx.y * 128);
}

// ---------------------------------------------------------------------------
// RoPE: sin/cos table once per (b,t,i), then bandwidth-only apply
// ---------------------------------------------------------------------------
struct TsTab { double ts[64]; };

__global__ void rope_table(const int* __restrict__ pos, TsTab tt)
{
    int idx = blockIdx.x * blockDim.x + threadIdx.x; // B*T*64
    int i = idx & 63;
    int t = (idx >> 6) & (TT - 1);
    int b = idx >> 17;
    double th = (double)pos[b * TT + t] * tt.ts[i];
    double sd, cd;
    sincos(th, &sd, &cd);
    g_tab[idx] = make_float2((float)cd, (float)sd);
}

__global__ void rope_apply(float* __restrict__ buf, int nheads, int strideHeads,
                           float scale)
{
    int idx = blockIdx.x * blockDim.x + threadIdx.x;
    int i = idx & 63;
    int t = (idx >> 6) & (TT - 1);
    int rest = idx >> 17;
    int hd = rest % nheads;
    int b = rest / nheads;
    if (b >= BB) return;
    float2 cs = g_tab[((size_t)b * TT + t) * 64 + i];
    size_t base = (((size_t)(b * strideHeads + hd)) * TT + t) * HDIM;
    float f = buf[base + i];
    float se = buf[base + 64 + i];
    buf[base + i] = (f * cs.x - se * cs.y) * scale;
    buf[base + 64 + i] = (se * cs.x + f * cs.y) * scale;
}

// ---------------------------------------------------------------------------
// Flash attention: 64 q-rows/block, 64-wide KV tiles, causal + softcap,
// shuffle-based row stats (rows live in 16-lane groups). 256 threads.
// ---------------------------------------------------------------------------
#define PS_LD 65
#define SMEM_ATTN ((128 * 64 * 2 + 64 * 128 + 64 * PS_LD) * 4)

__global__ __launch_bounds__(256) void attn_kernel()
{
    extern __shared__ float sm[];
    float* Qt = sm;              // [128][64]
    float* Kt = Qt + 128 * 64;   // [128][64]
    float* Vs = Kt + 128 * 64;   // [64][128]
    float* Ps = Vs + 64 * 128;   // [64][PS_LD]

    const int tid = threadIdx.x;
    const int tx = tid & 15, ty = tid >> 4;
    const int qi = gridDim.x - 1 - blockIdx.x;  // heavy blocks first
    const int q0 = qi * 64;
    const int n = blockIdx.y, b = blockIdx.z;
    const int kvh = n >> 1;
    const float* Qp = g_q + ((size_t)(b * NHEADS + n)) * TT * HDIM;
    const float* Kp = g_kv + ((size_t)(b * 16 + kvh)) * TT * HDIM;
    const float* Vp = g_kv + ((size_t)(b * 16 + 8 + kvh)) * TT * HDIM;

    // load Q tile transposed
    {
        int c = tid & 63, k4 = (tid >> 6) << 2;
#pragma unroll
        for (int kb = 0; kb < 8; kb++) {
            int k = kb * 16 + k4;
            float4 v = *(const float4*)(Qp + (size_t)(q0 + c) * HDIM + k);
            Qt[(k + 0) * 64 + c] = v.x;
            Qt[(k + 1) * 64 + c] = v.y;
            Qt[(k + 2) * 64 + c] = v.z;
            Qt[(k + 3) * 64 + c] = v.w;
        }
    }

    float mreg[4], lreg[4];
    float o[4][8];
#pragma unroll
    for (int i = 0; i < 4; i++) {
        mreg[i] = -3.0e38f; lreg[i] = 0.0f;
#pragma unroll
        for (int j = 0; j < 8; j++) o[i][j] = 0.0f;
    }

    for (int tile = 0; tile <= qi; tile++) {
        const int s0 = tile * 64;
        __syncthreads(); // prev reads of Kt/Vs/Ps done
        {
            int c = tid & 63, k4 = (tid >> 6) << 2;
#pragma unroll
            for (int kb = 0; kb < 8; kb++) {
                int k = kb * 16 + k4;
                float4 v = *(const float4*)(Kp + (size_t)(s0 + c) * HDIM + k);
                Kt[(k + 0) * 64 + c] = v.x;
                Kt[(k + 1) * 64 + c] = v.y;
                Kt[(k + 2) * 64 + c] = v.z;
                Kt[(k + 3) * 64 + c] = v.w;
            }
#pragma unroll
            for (int it = 0; it < 8; it++) {
                int idx4 = tid + it * 256;
                int s = idx4 >> 5, c4 = (idx4 & 31) << 2;
                *(float4*)(Vs + s * 128 + c4) =
                    *(const float4*)(Vp + (size_t)(s0 + s) * HDIM + c4);
            }
        }
        __syncthreads();

        // S = Q K^T (64x64), 4x4 per thread
        float sa[4][4];
#pragma unroll
        for (int i = 0; i < 4; i++)
#pragma unroll
            for (int j = 0; j < 4; j++) sa[i][j] = 0.0f;
#pragma unroll 8
        for (int k = 0; k < 128; k++) {
            float4 a4 = *(const float4*)(Qt + k * 64 + ty * 4);
            float4 b4 = *(const float4*)(Kt + k * 64 + tx * 4);
            const float av[4] = {a4.x, a4.y, a4.z, a4.w};
            const float bv[4] = {b4.x, b4.y, b4.z, b4.w};
#pragma unroll
            for (int i = 0; i < 4; i++)
#pragma unroll
                for (int j = 0; j < 4; j++)
                    sa[i][j] = fmaf(av[i], bv[j], sa[i][j]);
        }

        // softcap + mask + online softmax row stats via 16-lane shuffles
#pragma unroll
        for (int i = 0; i < 4; i++) {
            const int tq = q0 + ty * 4 + i;
#pragma unroll
            for (int j = 0; j < 4; j++) {
                float v = 50.0f * tanhf(sa[i][j] * 0.02f);
                if (s0 + tx * 4 + j > tq) v = -2.3819763e38f;
                sa[i][j] = v;
            }
            float mx = fmaxf(fmaxf(sa[i][0], sa[i][1]), fmaxf(sa[i][2], sa[i][3]));
            mx = fmaxf(mx, __shfl_xor_sync(0xffffffffu, mx, 1));
            mx = fmaxf(mx, __shfl_xor_sync(0xffffffffu, mx, 2));
            mx = fmaxf(mx, __shfl_xor_sync(0xffffffffu, mx, 4));
            mx = fmaxf(mx, __shfl_xor_sync(0xffffffffu, mx, 8));
            float mnew = fmaxf(mreg[i], mx);
            float alpha = __expf(mreg[i] - mnew);
            mreg[i] = mnew;
            float ssum = 0.0f;
#pragma unroll
            for (int j = 0; j < 4; j++) {
                float p = __expf(sa[i][j] - mnew);
                Ps[(ty * 4 + i) * PS_LD + tx * 4 + j] = p;
                ssum += p;
            }
            ssum += __shfl_xor_sync(0xffffffffu, ssum, 1);
            ssum += __shfl_xor_sync(0xffffffffu, ssum, 2);
            ssum += __shfl_xor_sync(0xffffffffu, ssum, 4);
            ssum += __shfl_xor_sync(0xffffffffu, ssum, 8);
            lreg[i] = lreg[i] * alpha + ssum;
#pragma unroll
            for (int j = 0; j < 8; j++) o[i][j] *= alpha;
        }
        __syncthreads();

        // O += P V
#pragma unroll 4
        for (int s = 0; s < 64; s++) {
            float p0 = Ps[(ty * 4 + 0) * PS_LD + s];
            float p1 = Ps[(ty * 4 + 1) * PS_LD + s];
            float p2 = Ps[(ty * 4 + 2) * PS_LD + s];
            float p3 = Ps[(ty * 4 + 3) * PS_LD + s];
#pragma unroll
            for (int j = 0; j < 8; j++) {
                float vv = Vs[s * 128 + tx + 16 * j];
                o[0][j] = fmaf(p0, vv, o[0][j]);
                o[1][j] = fmaf(p1, vv, o[1][j]);
                o[2][j] = fmaf(p2, vv, o[2][j]);
                o[3][j] = fmaf(p3, vv, o[3][j]);
            }
        }
    }

#pragma unroll
    for (int i = 0; i < 4; i++) {
        float inv = 1.0f / lreg[i];
        size_t rowb = ((size_t)b * TT + q0 + ty * 4 + i) * (NHEADS * HDIM) + n * HDIM;
#pragma unroll
        for (int j = 0; j < 8; j++)
            g_enc[rowb + tx + 16 * j] = o[i][j] * inv;
    }
}

// ---------------------------------------------------------------------------
extern "C" void kernel_launch(void* const* d_in, const int* in_sizes, int n_in,
                              void* d_out, int out_size)
{
    const float* x = (const float*)d_in[0];
    const int* positions = (const int*)d_in[1];
    // d_in[2] = attn_mask (causal) — analytic
    const float* w_q = (const float*)d_in[3];
    const float* w_kv = (const float*)d_in[4];
    const float* w_out = (const float*)d_in[5];
    float* out = (float*)d_out;

    float *qb = nullptr, *kvb = nullptr;
    cudaGetSymbolAddress((void**)&qb, g_q);
    cudaGetSymbolAddress((void**)&kvb, g_kv);

    // rope timescales (host double math, deterministic)
    TsTab tt;
    for (int i = 0; i < 64; i++) tt.ts[i] = pow(10000.0, -(double)i / 64.0);

    rope_table<<<(BB * TT * 64) / 256, 256>>>(positions, tt);

    // projections (tf32 tensor cores)
    proj_tf32<<<dim3(TT / 128, BB * NHEADS), 256>>>(x, w_q, qb, NHEADS);
    proj_tf32<<<dim3(TT / 128, BB * 16), 256>>>(x, w_kv, kvb, 16);

    // rope apply: q (scaled by H^-0.5), k (heads 0..7 of kv buffer)
    rope_apply<<<(BB * NHEADS * TT * 64) / 256, 256>>>(
        qb, NHEADS, NHEADS, 0.08838834764831845f);
    rope_apply<<<(BB * NKVH * TT * 64) / 256, 256>>>(
        kvb, NKVH, 16, 1.0f);

    // flash attention
    cudaFuncSetAttribute(attn_kernel, cudaFuncAttributeMaxDynamicSharedMemorySize,
                         SMEM_ATTN);
    attn_kernel<<<dim3(TT / 64, NHEADS, BB), 256, SMEM_ATTN>>>();

    // output projection (tf32)
    outproj_tf32<<<dim3((BB * TT) / 128, DD / 128), 256>>>(w_out, out);
}

// round 3
// speedup vs baseline: 3.5705x; 1.5713x over previous
#include <cuda_runtime.h>
#include <math.h>
#include <stdint.h>

#define BB 2
#define TT 2048
#define DD 2048
#define NHEADS 16
#define NKVH 8
#define HDIM 128

// Scratch (allocation-free rule: __device__ globals)
static __device__ float g_q[(size_t)BB * NHEADS * TT * HDIM];   // [b][n][t][h]
static __device__ float g_kv[(size_t)BB * 16 * TT * HDIM];      // [b][j][t][h], j<8=K, j>=8=V
static __device__ float g_enc[(size_t)BB * TT * NHEADS * HDIM]; // [b][t][n*128+h]
static __device__ float2 g_tab[(size_t)BB * TT * 64];           // rope cos/sin

// ---------------------------------------------------------------------------
// tf32 helpers
// ---------------------------------------------------------------------------
__device__ __forceinline__ float tf32r(float x) {
    uint32_t u;
    asm("cvt.rna.tf32.f32 %0, %1;" : "=r"(u) : "f"(x));
    return __uint_as_float(u);
}
__device__ __forceinline__ uint32_t smem_u32(const void* p) {
    return (uint32_t)__cvta_generic_to_shared(p);
}
__device__ __forceinline__ void ldm4(uint32_t* r, uint32_t addr) {
    asm volatile("ldmatrix.sync.aligned.m8n8.x4.shared.b16 {%0,%1,%2,%3}, [%4];"
                 : "=r"(r[0]), "=r"(r[1]), "=r"(r[2]), "=r"(r[3]) : "r"(addr));
}
__device__ __forceinline__ void mma_tf32(float* d, const uint32_t* a, const uint32_t* b) {
    asm volatile(
        "mma.sync.aligned.m16n8k8.row.col.f32.tf32.tf32.f32 "
        "{%0,%1,%2,%3}, {%4,%5,%6,%7}, {%8,%9}, {%0,%1,%2,%3};"
        : "+f"(d[0]), "+f"(d[1]), "+f"(d[2]), "+f"(d[3])
        : "r"(a[0]), "r"(a[1]), "r"(a[2]), "r"(a[3]), "r"(b[0]), "r"(b[1]));
}

// ---------------------------------------------------------------------------
// tf32 GEMM body: 128x128 tile, BK=32, 256 threads (8 warps, 4x2 grid)
// ---------------------------------------------------------------------------
#define ALD 36
#define BLD 136

__device__ __forceinline__ void gemm_tf32_body(
    const float* __restrict__ A, int lda,
    const float* __restrict__ B, int ldb,
    float* __restrict__ C, int ldc,
    int K, int m0, int n0)
{
    __shared__ float As[128 * ALD];
    __shared__ float Bs[32 * BLD];
    const int tid = threadIdx.x;
    const int lane = tid & 31, warp = tid >> 5;
    const int m_warp = (warp & 3) * 32, n_warp = (warp >> 2) * 64;

    int aoff[4], asm_[4], boff[4], bsm_[4];
#pragma unroll
    for (int i = 0; i < 4; i++) {
        int idx = tid + i * 256;
        int m = idx >> 3, k4 = (idx & 7) * 4;
        aoff[i] = (m0 + m) * lda + k4;
        asm_[i] = m * ALD + k4;
        int kb = idx >> 5, n4 = (idx & 31) * 4;
        boff[i] = kb * ldb + n0 + n4;
        bsm_[i] = kb * BLD + n4;
    }

    uint32_t aAddr[2];
    {
        uint32_t baseA = smem_u32(As);
        int r = lane & 15;
        int cA = (lane & 16) ? 4 : 0;
#pragma unroll
        for (int mt = 0; mt < 2; mt++)
            aAddr[mt] = baseA + (uint32_t)((m_warp + mt * 16 + r) * ALD + cA) * 4u;
    }
    const int bk = lane & 3, bn = n_warp + (lane >> 2);

    float acc[2][8][4];
#pragma unroll
    for (int mt = 0; mt < 2; mt++)
#pragma unroll
        for (int nt = 0; nt < 8; nt++)
#pragma unroll
            for (int e = 0; e < 4; e++) acc[mt][nt][e] = 0.0f;

    float4 ra[4], rb[4];
#pragma unroll
    for (int i = 0; i < 4; i++) {
        ra[i] = *(const float4*)(A + aoff[i]);
        rb[i] = *(const float4*)(B + boff[i]);
    }

    for (int k0 = 0; k0 < K; k0 += 32) {
        __syncthreads();
#pragma unroll
        for (int i = 0; i < 4; i++) {
            float4 v = ra[i];
            v.x = tf32r(v.x); v.y = tf32r(v.y); v.z = tf32r(v.z); v.w = tf32r(v.w);
            *(float4*)&As[asm_[i]] = v;
            float4 w = rb[i];
            w.x = tf32r(w.x); w.y = tf32r(w.y); w.z = tf32r(w.z); w.w = tf32r(w.w);
            *(float4*)&Bs[bsm_[i]] = w;
        }
        __syncthreads();
        if (k0 + 32 < K) {
#pragma unroll
            for (int i = 0; i < 4; i++) {
                ra[i] = *(const float4*)(A + aoff[i] + k0 + 32);
                rb[i] = *(const float4*)(B + boff[i] + (k0 + 32) * ldb);
            }
        }
#pragma unroll
        for (int k8 = 0; k8 < 4; k8++) {
            uint32_t af[2][4];
#pragma unroll
            for (int mt = 0; mt < 2; mt++) ldm4(af[mt], aAddr[mt] + (uint32_t)k8 * 32u);
            uint32_t bf[8][2];
#pragma unroll
            for (int nt = 0; nt < 8; nt++) {
                bf[nt][0] = __float_as_uint(Bs[(k8 * 8 + bk) * BLD + bn + nt * 8]);
                bf[nt][1] = __float_as_uint(Bs[(k8 * 8 + 4 + bk) * BLD + bn + nt * 8]);
            }
#pragma unroll
            for (int mt = 0; mt < 2; mt++)
#pragma unroll
                for (int nt = 0; nt < 8; nt++)
                    mma_tf32(acc[mt][nt], af[mt], bf[nt]);
        }
    }

    const int r = lane >> 2, cq = (lane & 3) * 2;
#pragma unroll
    for (int mt = 0; mt < 2; mt++) {
        int row = m0 + m_warp + mt * 16 + r;
#pragma unroll
        for (int nt = 0; nt < 8; nt++) {
            int col = n0 + n_warp + nt * 8 + cq;
            *(float2*)&C[(size_t)row * ldc + col] = make_float2(acc[mt][nt][0], acc[mt][nt][1]);
            *(float2*)&C[(size_t)(row + 8) * ldc + col] = make_float2(acc[mt][nt][2], acc[mt][nt][3]);
        }
    }
}

__global__ __launch_bounds__(256) void proj_tf32(
    const float* __restrict__ x, const float* __restrict__ W,
    float* __restrict__ out, int nheads)
{
    const int bh = blockIdx.y;
    const int b = bh / nheads, h = bh % nheads;
    gemm_tf32_body(x + (size_t)b * TT * DD, DD,
                   W + (size_t)h * DD * HDIM, HDIM,
                   out + (size_t)bh * TT * HDIM, HDIM,
                   DD, blockIdx.x * 128, 0);
}

__global__ __launch_bounds__(256) void outproj_tf32(
    const float* __restrict__ w_out, float* __restrict__ out)
{
    gemm_tf32_body(g_enc, NHEADS * HDIM, w_out, DD, out, DD,
                   NHEADS * HDIM, blockIdx.x * 128, blockIdx.y * 128);
}

// ---------------------------------------------------------------------------
// RoPE
// ---------------------------------------------------------------------------
struct TsTab { double ts[64]; };

__global__ void rope_table(const int* __restrict__ pos, TsTab tt)
{
    int idx = blockIdx.x * blockDim.x + threadIdx.x;
    int i = idx & 63;
    int t = (idx >> 6) & (TT - 1);
    int b = idx >> 17;
    double th = (double)pos[b * TT + t] * tt.ts[i];
    double sd, cd;
    sincos(th, &sd, &cd);
    g_tab[idx] = make_float2((float)cd, (float)sd);
}

__global__ void rope_apply(float* __restrict__ buf, int nheads, int strideHeads,
                           float scale)
{
    int idx = blockIdx.x * blockDim.x + threadIdx.x;
    int i = idx & 63;
    int t = (idx >> 6) & (TT - 1);
    int rest = idx >> 17;
    int hd = rest % nheads;
    int b = rest / nheads;
    if (b >= BB) return;
    float2 cs = g_tab[((size_t)b * TT + t) * 64 + i];
    size_t base = (((size_t)(b * strideHeads + hd)) * TT + t) * HDIM;
    float f = buf[base + i];
    float se = buf[base + 64 + i];
    buf[base + i] = (f * cs.x - se * cs.y) * scale;
    buf[base + 64 + i] = (se * cs.x + f * cs.y) * scale;
}

// ---------------------------------------------------------------------------
// softcap + static-shift exp, MUFU-free.
// p = exp(50*tanh(x/50) - 13); capped<=50 so no overflow; masked -> 0.
// ---------------------------------------------------------------------------
__device__ __forceinline__ float softexp(float x, bool valid) {
    float y = x * 0.02f;
    float u = y * y;
    // odd Taylor of tanh through y^11 (|y| <~ 0.58 in practice)
    float pl = fmaf(u, -0.00886324f, 0.02186949f);
    pl = fmaf(u, pl, -0.05396825f);
    pl = fmaf(u, pl, 0.13333333f);
    pl = fmaf(u, pl, -0.33333333f);
    pl = fmaf(u, pl, 1.0f);
    float cap = x * pl; // 50*tanh(x/50)
    if (fabsf(y) > 0.58f) { // rare exact path
        float t = __expf(2.0f * fabsf(y));
        float th = 1.0f - __fdividef(2.0f, t + 1.0f);
        cap = copysignf(50.0f * th, x);
    }
    // exp(cap - 13) via software exp2 (FMA/ALU pipes only)
    float t = fmaf(cap, 1.442695041f, -18.755036f);
    float rr = t + 12582912.0f;            // round-to-nearest-int trick
    float nf = rr - 12582912.0f;
    float f = t - nf;
    float e = fmaf(f, 1.5403530e-4f, 1.3333558e-3f);
    e = fmaf(f, e, 9.6181291e-3f);
    e = fmaf(f, e, 5.5504109e-2f);
    e = fmaf(f, e, 2.4022651e-1f);
    e = fmaf(f, e, 6.9314718e-1f);
    e = fmaf(f, e, 1.0f);
    int ni = (__float_as_int(rr) & 0x7FFFFF) - 0x400000; // n in [-91,54]
    float sc = __int_as_float((ni + 127) << 23);
    return valid ? e * sc : 0.0f;
}

// ---------------------------------------------------------------------------
// Tensor-core flash attention: 64 q-rows/block (4 warps x 16), KV tiles of 64,
// tf32 mma for S and PV, static-shift softmax (no online max), causal.
// ---------------------------------------------------------------------------
#define KTLD 72   // Kt row stride (floats): [hd][kv]
#define VSLD 136  // Vs row stride: [kv][hd]
#define PSLD 68   // Ps row stride: [q][kv]
#define QSLD 132  // Qs row stride (init, aliased)
#define SMEM_ATTN ((128 * KTLD + 64 * VSLD + 64 * PSLD) * 4)

__global__ __launch_bounds__(128, 2) void attn_kernel()
{
    extern __shared__ float sm[];
    float* Kt = sm;                    // [128][KTLD]
    float* Vs = sm + 128 * KTLD;       // [64][VSLD]
    float* Ps = Vs + 64 * VSLD;        // [64][PSLD]
    float* Qs = sm;                    // alias (used only before loop)

    const int tid = threadIdx.x;
    const int lane = tid & 31, warp = tid >> 5;
    const int wm = warp * 16;
    const int lr = lane >> 2, lc = (lane & 3) * 2;
    const int qi = gridDim.x - 1 - blockIdx.x;  // heavy blocks first
    const int q0 = qi * 64;
    const int n = blockIdx.y, b = blockIdx.z;
    const int kvh = n >> 1;
    const float* Qp = g_q + ((size_t)(b * NHEADS + n)) * TT * HDIM;
    const float* Kp = g_kv + ((size_t)(b * 16 + kvh)) * TT * HDIM;
    const float* Vp = g_kv + ((size_t)(b * 16 + 8 + kvh)) * TT * HDIM;

    // ---- Q tile -> smem (tf32) -> ldmatrix into persistent regs
    {
        int c = tid & 63, k4 = (tid >> 6) << 2;
#pragma unroll
        for (int kb = 0; kb < 16; kb++) {
            int k = kb * 8 + k4;
            float4 v = *(const float4*)(Qp + (size_t)(q0 + c) * HDIM + k);
            v.x = tf32r(v.x); v.y = tf32r(v.y); v.z = tf32r(v.z); v.w = tf32r(v.w);
            *(float4*)&Qs[c * QSLD + k] = v;
        }
    }
    __syncthreads();
    uint32_t qf[16][4];
    {
        uint32_t baseQ = smem_u32(Qs);
        int r = lane & 15, cA = (lane & 16) ? 4 : 0;
        uint32_t addr = baseQ + (uint32_t)((wm + r) * QSLD + cA) * 4u;
#pragma unroll
        for (int k8 = 0; k8 < 16; k8++) ldm4(qf[k8], addr + (uint32_t)k8 * 32u);
    }
    __syncthreads();

    float o[16][4];
#pragma unroll
    for (int nt = 0; nt < 16; nt++)
#pragma unroll
        for (int e = 0; e < 4; e++) o[nt][e] = 0.0f;
    float ls0 = 0.0f, ls1 = 0.0f;

    const int gr0 = q0 + wm + lr;  // global q row (d0/d1)
    const int gr1 = gr0 + 8;       // global q row (d2/d3)
    const uint32_t psAddr = smem_u32(Ps) +
        (uint32_t)(((wm + (lane & 15)) * PSLD + ((lane >> 4) << 2)) * 4);

    for (int tile = 0; tile <= qi; tile++) {
        const int s0 = tile * 64;
        // load K transposed [hd][kv] + V [kv][hd], tf32
        {
            int c = tid & 63, k4 = (tid >> 6) << 2;
#pragma unroll
            for (int kb = 0; kb < 16; kb++) {
                int k = kb * 8 + k4;
                float4 v = *(const float4*)(Kp + (size_t)(s0 + c) * HDIM + k);
                Kt[(k + 0) * KTLD + c] = tf32r(v.x);
                Kt[(k + 1) * KTLD + c] = tf32r(v.y);
                Kt[(k + 2) * KTLD + c] = tf32r(v.z);
                Kt[(k + 3) * KTLD + c] = tf32r(v.w);
            }
#pragma unroll
            for (int it = 0; it < 16; it++) {
                int idx = tid + it * 128;
                int s = idx >> 5, c4 = (idx & 31) << 2;
                float4 v = *(const float4*)(Vp + (size_t)(s0 + s) * HDIM + c4);
                v.x = tf32r(v.x); v.y = tf32r(v.y); v.z = tf32r(v.z); v.w = tf32r(v.w);
                *(float4*)&Vs[s * VSLD + c4] = v;
            }
        }
        __syncthreads();

        // S = Q K^T (per warp: 16 rows x 64 cols)
        float sa[8][4];
#pragma unroll
        for (int nt = 0; nt < 8; nt++)
#pragma unroll
            for (int e = 0; e < 4; e++) sa[nt][e] = 0.0f;
#pragma unroll
        for (int k8 = 0; k8 < 16; k8++) {
            const int kr0 = (k8 * 8 + (lane & 3)) * KTLD + lr;
            uint32_t bfr[8][2];
#pragma unroll
            for (int nt = 0; nt < 8; nt++) {
                bfr[nt][0] = __float_as_uint(Kt[kr0 + nt * 8]);
                bfr[nt][1] = __float_as_uint(Kt[kr0 + 4 * KTLD + nt * 8]);
            }
#pragma unroll
            for (int nt = 0; nt < 8; nt++) mma_tf32(sa[nt], qf[k8], bfr[nt]);
        }

        // softcap + exp(s-13), causal mask, stash P (tf32) + row-sum accum
        float* psrow0 = Ps + (wm + lr) * PSLD + lc;
        float* psrow1 = psrow0 + 8 * PSLD;
#pragma unroll
        for (int nt = 0; nt < 8; nt++) {
            int c = s0 + nt * 8 + lc;
            float p00 = softexp(sa[nt][0], c <= gr0);
            float p01 = softexp(sa[nt][1], c + 1 <= gr0);
            float p10 = softexp(sa[nt][2], c <= gr1);
            float p11 = softexp(sa[nt][3], c + 1 <= gr1);
            ls0 += p00 + p01;
            ls1 += p10 + p11;
            *(float2*)(psrow0 + nt * 8) = make_float2(tf32r(p00), tf32r(p01));
            *(float2*)(psrow1 + nt * 8) = make_float2(tf32r(p10), tf32r(p11));
        }
        __syncthreads();

        // O += P V  (per warp: 16 rows x 128 cols)
#pragma unroll
        for (int k8 = 0; k8 < 8; k8++) {
            uint32_t pf[4];
            ldm4(pf, psAddr + (uint32_t)k8 * 32u);
            const int vr0 = (k8 * 8 + (lane & 3)) * VSLD + lr;
#pragma unroll
            for (int nt = 0; nt < 16; nt++) {
                uint32_t bb[2];
                bb[0] = __float_as_uint(Vs[vr0 + nt * 8]);
                bb[1] = __float_as_uint(Vs[vr0 + 4 * VSLD + nt * 8]);
                mma_tf32(o[nt], pf, bb);
            }
        }
        __syncthreads(); // protect Kt/Vs/Ps before next tile's stores
    }

    // finalize: l = quad sum, O /= l, write encoded
    ls0 += __shfl_xor_sync(0xffffffffu, ls0, 1);
    ls0 += __shfl_xor_sync(0xffffffffu, ls0, 2);
    ls1 += __shfl_xor_sync(0xffffffffu, ls1, 1);
    ls1 += __shfl_xor_sync(0xffffffffu, ls1, 2);
    float i0 = 1.0f / ls0, i1 = 1.0f / ls1;
    float* er0 = g_enc + ((size_t)b * TT + gr0) * (NHEADS * HDIM) + n * HDIM + lc;
    float* er1 = g_enc + ((size_t)b * TT + gr1) * (NHEADS * HDIM) + n * HDIM + lc;
#pragma unroll
    for (int nt = 0; nt < 16; nt++) {
        *(float2*)(er0 + nt * 8) = make_float2(o[nt][0] * i0, o[nt][1] * i0);
        *(float2*)(er1 + nt * 8) = make_float2(o[nt][2] * i1, o[nt][3] * i1);
    }
}

// ---------------------------------------------------------------------------
extern "C" void kernel_launch(void* const* d_in, const int* in_sizes, int n_in,
                              void* d_out, int out_size)
{
    const float* x = (const float*)d_in[0];
    const int* positions = (const int*)d_in[1];
    // d_in[2] = attn_mask (causal) — analytic
    const float* w_q = (const float*)d_in[3];
    const float* w_kv = (const float*)d_in[4];
    const float* w_out = (const float*)d_in[5];
    float* out = (float*)d_out;

    float *qb = nullptr, *kvb = nullptr;
    cudaGetSymbolAddress((void**)&qb, g_q);
    cudaGetSymbolAddress((void**)&kvb, g_kv);

    TsTab tt;
    for (int i = 0; i < 64; i++) tt.ts[i] = pow(10000.0, -(double)i / 64.0);

    rope_table<<<(BB * TT * 64) / 256, 256>>>(positions, tt);

    proj_tf32<<<dim3(TT / 128, BB * NHEADS), 256>>>(x, w_q, qb, NHEADS);
    proj_tf32<<<dim3(TT / 128, BB * 16), 256>>>(x, w_kv, kvb, 16);

    rope_apply<<<(BB * NHEADS * TT * 64) / 256, 256>>>(
        qb, NHEADS, NHEADS, 0.08838834764831845f);
    rope_apply<<<(BB * NKVH * TT * 64) / 256, 256>>>(
        kvb, NKVH, 16, 1.0f);

    cudaFuncSetAttribute(attn_kernel, cudaFuncAttributeMaxDynamicSharedMemorySize,
                         SMEM_ATTN);
    attn_kernel<<<dim3(TT / 64, NHEADS, BB), 128, SMEM_ATTN>>>();

    outproj_tf32<<<dim3((BB * TT) / 128, DD / 128), 256>>>(w_out, out);
}

// round 5
// speedup vs baseline: 4.2838x; 1.1998x over previous
#include <cuda_runtime.h>
#include <math.h>
#include <stdint.h>

#define BB 2
#define TT 2048
#define DD 2048
#define NHEADS 16
#define NKVH 8
#define HDIM 128

// Scratch (allocation-free rule: __device__ globals)
static __device__ float g_q[(size_t)BB * NHEADS * TT * HDIM];   // [b][n][t][h]
static __device__ float g_kv[(size_t)BB * 16 * TT * HDIM];      // [b][j][t][h], j<8=K, j>=8=V
static __device__ float g_enc[(size_t)BB * TT * NHEADS * HDIM]; // [b][t][n*128+h] (tf32-rounded)
static __device__ float2 g_tab[(size_t)BB * TT * 64];           // rope cos/sin
static __device__ float g_xr[(size_t)BB * TT * DD];             // x, tf32-rounded
static __device__ float g_wqr[(size_t)NHEADS * DD * HDIM];      // w_q, tf32-rounded
static __device__ float g_wkvr[(size_t)2 * NKVH * DD * HDIM];   // w_kv, tf32-rounded
static __device__ float g_wor[(size_t)DD * DD];                 // w_out, tf32-rounded

// ---------------------------------------------------------------------------
// helpers
// ---------------------------------------------------------------------------
__device__ __forceinline__ float tf32r(float x) {
    uint32_t u;
    asm("cvt.rna.tf32.f32 %0, %1;" : "=r"(u) : "f"(x));
    return __uint_as_float(u);
}
__device__ __forceinline__ uint32_t smem_u32(const void* p) {
    return (uint32_t)__cvta_generic_to_shared(p);
}
__device__ __forceinline__ void ldm4(uint32_t* r, uint32_t addr) {
    asm volatile("ldmatrix.sync.aligned.m8n8.x4.shared.b16 {%0,%1,%2,%3}, [%4];"
                 : "=r"(r[0]), "=r"(r[1]), "=r"(r[2]), "=r"(r[3]) : "r"(addr));
}
__device__ __forceinline__ void mma_tf32(float* d, const uint32_t* a, const uint32_t* b) {
    asm volatile(
        "mma.sync.aligned.m16n8k8.row.col.f32.tf32.tf32.f32 "
        "{%0,%1,%2,%3}, {%4,%5,%6,%7}, {%8,%9}, {%0,%1,%2,%3};"
        : "+f"(d[0]), "+f"(d[1]), "+f"(d[2]), "+f"(d[3])
        : "r"(a[0]), "r"(a[1]), "r"(a[2]), "r"(a[3]), "r"(b[0]), "r"(b[1]));
}
__device__ __forceinline__ void cpa16(uint32_t dst, const float* src) {
    asm volatile("cp.async.cg.shared.global [%0], [%1], 16;"
                 :: "r"(dst), "l"(src) : "memory");
}
__device__ __forceinline__ void cpa_commit() {
    asm volatile("cp.async.commit_group;" ::: "memory");
}
template <int N> __device__ __forceinline__ void cpa_wait() {
    asm volatile("cp.async.wait_group %0;" :: "n"(N) : "memory");
}

// ---------------------------------------------------------------------------
// tf32 GEMM: 128x128 tile, BK=16, 3-stage cp.async pipeline, 256 threads
// (8 warps, 4x2), warp tile 32x64, occupancy 2. Inputs MUST be tf32-pre-
// rounded (cp.async bypasses registers; the MMA truncates raw fp32).
// A row-major [M,K], B row-major [K,N].
// ---------------------------------------------------------------------------
#define ALD 20       // As row stride (16 k floats + 4 pad)
#define BLD 136      // Bs row stride
#define NSTG 3
#define A_STG (128 * ALD)   // floats per A stage
#define B_STG (16 * BLD)    // floats per B stage
#define GSMEM ((NSTG * (A_STG + B_STG)) * 4)  // 56832 B

__device__ __forceinline__ void gemm_body(
    const float* __restrict__ A, int lda,
    const float* __restrict__ B, int ldb,
    float* __restrict__ C, int ldc,
    int K, int m0, int n0)
{
    extern __shared__ float smg[];
    float* As = smg;                  // [NSTG][128][ALD]
    float* Bs = smg + NSTG * A_STG;   // [NSTG][16][BLD]
    const int tid = threadIdx.x;
    const int lane = tid & 31, warp = tid >> 5;
    const int m_warp = (warp & 3) * 32, n_warp = (warp >> 2) * 64;

    // loader lane mapping
    const int la_row = tid >> 2, la_k4 = (tid & 3) * 4;          // A: idx=tid (+256)
    const int lb_kb = tid >> 5, lb_n4 = (tid & 31) * 4;          // B: idx=tid (+256)
    const float* Ap = A + (size_t)(m0 + la_row) * lda + la_k4;
    const float* Ap2 = A + (size_t)(m0 + la_row + 64) * lda + la_k4;
    const float* Bp = B + (size_t)lb_kb * ldb + n0 + lb_n4;
    const float* Bp2 = B + (size_t)(lb_kb + 8) * ldb + n0 + lb_n4;
    const uint32_t asm1 = (uint32_t)(la_row * ALD + la_k4) * 4u;
    const uint32_t asm2 = (uint32_t)((la_row + 64) * ALD + la_k4) * 4u;
    const uint32_t bsm1 = (uint32_t)(lb_kb * BLD + lb_n4) * 4u;
    const uint32_t bsm2 = (uint32_t)((lb_kb + 8) * BLD + lb_n4) * 4u;
    const uint32_t aBase = smem_u32(As), bBase = smem_u32(Bs);

    // ldmatrix A lane addressing (tf32-as-2xb16 trick, same as R3)
    const uint32_t aLane =
        (uint32_t)((m_warp + (lane & 15)) * ALD + ((lane & 16) ? 4 : 0)) * 4u;
    const int bk = lane & 3, bn = n_warp + (lane >> 2);

    float acc[2][8][4];
#pragma unroll
    for (int mt = 0; mt < 2; mt++)
#pragma unroll
        for (int nt = 0; nt < 8; nt++)
#pragma unroll
            for (int e = 0; e < 4; e++) acc[mt][nt][e] = 0.0f;

    const int NC = K >> 4;  // BK=16 chunks

    // prologue: stages 0..NSTG-2
#pragma unroll
    for (int p = 0; p < NSTG - 1; p++) {
        uint32_t ab = aBase + (uint32_t)(p * A_STG) * 4u;
        uint32_t bb = bBase + (uint32_t)(p * B_STG) * 4u;
        cpa16(ab + asm1, Ap + p * 16);
        cpa16(ab + asm2, Ap2 + p * 16);
        cpa16(bb + bsm1, Bp + (size_t)(p * 16) * ldb);
        cpa16(bb + bsm2, Bp2 + (size_t)(p * 16) * ldb);
        cpa_commit();
    }

    for (int c = 0; c < NC; c++) {
        const int s = c % NSTG;
        cpa_wait<NSTG - 2>();
        __syncthreads();
        // prefetch stage c+NSTG-1 (overwrites buffer computed at iter c-1)
        const int cn = c + NSTG - 1;
        if (cn < NC) {
            const int sn = cn % NSTG;
            uint32_t ab = aBase + (uint32_t)(sn * A_STG) * 4u;
            uint32_t bb = bBase + (uint32_t)(sn * B_STG) * 4u;
            cpa16(ab + asm1, Ap + cn * 16);
            cpa16(ab + asm2, Ap2 + cn * 16);
            cpa16(bb + bsm1, Bp + (size_t)(cn * 16) * ldb);
            cpa16(bb + bsm2, Bp2 + (size_t)(cn * 16) * ldb);
        }
        cpa_commit();  // keep group count in lockstep

        const uint32_t aSt = aBase + (uint32_t)(s * A_STG) * 4u + aLane;
        const float* bSt = Bs + s * B_STG;
#pragma unroll
        for (int k8 = 0; k8 < 2; k8++) {
            uint32_t af[2][4];
            ldm4(af[0], aSt + (uint32_t)k8 * 32u);
            ldm4(af[1], aSt + (uint32_t)(16 * ALD * 4) + (uint32_t)k8 * 32u);
            const int kr0 = (k8 * 8 + bk) * BLD + bn;
            uint32_t bf[8][2];
#pragma unroll
            for (int nt = 0; nt < 8; nt++) {
                bf[nt][0] = __float_as_uint(bSt[kr0 + nt * 8]);
                bf[nt][1] = __float_as_uint(bSt[kr0 + 4 * BLD + nt * 8]);
            }
#pragma unroll
            for (int mt = 0; mt < 2; mt++)
#pragma unroll
                for (int nt = 0; nt < 8; nt++)
                    mma_tf32(acc[mt][nt], af[mt], bf[nt]);
        }
    }

    const int r = lane >> 2, cq = (lane & 3) * 2;
#pragma unroll
    for (int mt = 0; mt < 2; mt++) {
        int row = m0 + m_warp + mt * 16 + r;
#pragma unroll
        for (int nt = 0; nt < 8; nt++) {
            int col = n0 + n_warp + nt * 8 + cq;
            *(float2*)&C[(size_t)row * ldc + col] = make_float2(acc[mt][nt][0], acc[mt][nt][1]);
            *(float2*)&C[(size_t)(row + 8) * ldc + col] = make_float2(acc[mt][nt][2], acc[mt][nt][3]);
        }
    }
}

// merged Q+KV projection: bh = b*32 + hh; hh<16 -> Q head, else KV "head"
__global__ __launch_bounds__(256, 2) void proj_merged()
{
    const int bh = blockIdx.y;
    const int b = bh >> 5, hh = bh & 31;
    const float* W;
    float* out;
    if (hh < 16) {
        W = g_wqr + (size_t)hh * DD * HDIM;
        out = g_q + ((size_t)(b * NHEADS + hh)) * TT * HDIM;
    } else {
        W = g_wkvr + (size_t)(hh - 16) * DD * HDIM;
        out = g_kv + ((size_t)(b * 16 + (hh - 16))) * TT * HDIM;
    }
    gemm_body(g_xr + (size_t)b * TT * DD, DD, W, HDIM, out, HDIM,
              DD, blockIdx.x * 128, 0);
}

__global__ __launch_bounds__(256, 2) void outproj(float* __restrict__ out)
{
    gemm_body(g_enc, NHEADS * HDIM, g_wor, DD, out, DD,
              NHEADS * HDIM, blockIdx.x * 128, blockIdx.y * 128);
}

// ---------------------------------------------------------------------------
// prep: tf32-rna round copies (zero-mean rounding; MMA truncates otherwise)
// ---------------------------------------------------------------------------
__global__ void round_copy(const float* __restrict__ src, float* __restrict__ dst)
{
    int i = blockIdx.x * 256 + threadIdx.x;
    float4 v = ((const float4*)src)[i];
    v.x = tf32r(v.x); v.y = tf32r(v.y); v.z = tf32r(v.z); v.w = tf32r(v.w);
    ((float4*)dst)[i] = v;
}

// ---------------------------------------------------------------------------
// RoPE
// ---------------------------------------------------------------------------
struct TsTab { double ts[64]; };

__global__ void rope_table(const int* __restrict__ pos, TsTab tt)
{
    int idx = blockIdx.x * blockDim.x + threadIdx.x;
    int i = idx & 63;
    int t = (idx >> 6) & (TT - 1);
    int b = idx >> 17;
    double th = (double)pos[b * TT + t] * tt.ts[i];
    double sd, cd;
    sincos(th, &sd, &cd);
    g_tab[idx] = make_float2((float)cd, (float)sd);
}

__global__ void rope_apply(float* __restrict__ buf, int nheads, int strideHeads,
                           float scale)
{
    int idx = blockIdx.x * blockDim.x + threadIdx.x;
    int i = idx & 63;
    int t = (idx >> 6) & (TT - 1);
    int rest = idx >> 17;
    int hd = rest % nheads;
    int b = rest / nheads;
    if (b >= BB) return;
    float2 cs = g_tab[((size_t)b * TT + t) * 64 + i];
    size_t base = (((size_t)(b * strideHeads + hd)) * TT + t) * HDIM;
    float f = buf[base + i];
    float se = buf[base + 64 + i];
    buf[base + i] = (f * cs.x - se * cs.y) * scale;
    buf[base + 64 + i] = (se * cs.x + f * cs.y) * scale;
}

// ---------------------------------------------------------------------------
// softcap + static-shift exp, MUFU-free.
// ---------------------------------------------------------------------------
__device__ __forceinline__ float softexp(float x, bool valid) {
    float y = x * 0.02f;
    float u = y * y;
    float pl = fmaf(u, -0.00886324f, 0.02186949f);
    pl = fmaf(u, pl, -0.05396825f);
    pl = fmaf(u, pl, 0.13333333f);
    pl = fmaf(u, pl, -0.33333333f);
    pl = fmaf(u, pl, 1.0f);
    float cap = x * pl;
    if (fabsf(y) > 0.58f) {
        float t = __expf(2.0f * fabsf(y));
        float th = 1.0f - __fdividef(2.0f, t + 1.0f);
        cap = copysignf(50.0f * th, x);
    }
    float t = fmaf(cap, 1.442695041f, -18.755036f);
    float rr = t + 12582912.0f;
    float nf = rr - 12582912.0f;
    float f = t - nf;
    float e = fmaf(f, 1.5403530e-4f, 1.3333558e-3f);
    e = fmaf(f, e, 9.6181291e-3f);
    e = fmaf(f, e, 5.5504109e-2f);
    e = fmaf(f, e, 2.4022651e-1f);
    e = fmaf(f, e, 6.9314718e-1f);
    e = fmaf(f, e, 1.0f);
    int ni = (__float_as_int(rr) & 0x7FFFFF) - 0x400000;
    float sc = __int_as_float((ni + 127) << 23);
    return valid ? e * sc : 0.0f;
}

// ---------------------------------------------------------------------------
// Tensor-core flash attention (mma.sync tf32). g_enc stores tf32-rounded
// (feeds cp.async outproj which truncates).
// ---------------------------------------------------------------------------
#define KTLD 72
#define VSLD 136
#define PSLD 68
#define QSLD 132
#define SMEM_ATTN ((128 * KTLD + 64 * VSLD + 64 * PSLD) * 4)

__global__ __launch_bounds__(128, 2) void attn_kernel()
{
    extern __shared__ float sm[];
    float* Kt = sm;
    float* Vs = sm + 128 * KTLD;
    float* Ps = Vs + 64 * VSLD;
    float* Qs = sm;

    const int tid = threadIdx.x;
    const int lane = tid & 31, warp = tid >> 5;
    const int wm = warp * 16;
    const int lr = lane >> 2, lc = (lane & 3) * 2;
    const int qi = gridDim.x - 1 - blockIdx.x;
    const int q0 = qi * 64;
    const int n = blockIdx.y, b = blockIdx.z;
    const int kvh = n >> 1;
    const float* Qp = g_q + ((size_t)(b * NHEADS + n)) * TT * HDIM;
    const float* Kp = g_kv + ((size_t)(b * 16 + kvh)) * TT * HDIM;
    const float* Vp = g_kv + ((size_t)(b * 16 + 8 + kvh)) * TT * HDIM;

    {
        int c = tid & 63, k4 = (tid >> 6) << 2;
#pragma unroll
        for (int kb = 0; kb < 16; kb++) {
            int k = kb * 8 + k4;
            float4 v = *(const float4*)(Qp + (size_t)(q0 + c) * HDIM + k);
            v.x = tf32r(v.x); v.y = tf32r(v.y); v.z = tf32r(v.z); v.w = tf32r(v.w);
            *(float4*)&Qs[c * QSLD + k] = v;
        }
    }
    __syncthreads();
    uint32_t qf[16][4];
    {
        uint32_t baseQ = smem_u32(Qs);
        int r = lane & 15, cA = (lane & 16) ? 4 : 0;
        uint32_t addr = baseQ + (uint32_t)((wm + r) * QSLD + cA) * 4u;
#pragma unroll
        for (int k8 = 0; k8 < 16; k8++) ldm4(qf[k8], addr + (uint32_t)k8 * 32u);
    }
    __syncthreads();

    float o[16][4];
#pragma unroll
    for (int nt = 0; nt < 16; nt++)
#pragma unroll
        for (int e = 0; e < 4; e++) o[nt][e] = 0.0f;
    float ls0 = 0.0f, ls1 = 0.0f;

    const int gr0 = q0 + wm + lr;
    const int gr1 = gr0 + 8;
    const uint32_t psAddr = smem_u32(Ps) +
        (uint32_t)(((wm + (lane & 15)) * PSLD + ((lane >> 4) << 2)) * 4);

    for (int tile = 0; tile <= qi; tile++) {
        const int s0 = tile * 64;
        {
            int c = tid & 63, k4 = (tid >> 6) << 2;
#pragma unroll
            for (int kb = 0; kb < 16; kb++) {
                int k = kb * 8 + k4;
                float4 v = *(const float4*)(Kp + (size_t)(s0 + c) * HDIM + k);
                Kt[(k + 0) * KTLD + c] = tf32r(v.x);
                Kt[(k + 1) * KTLD + c] = tf32r(v.y);
                Kt[(k + 2) * KTLD + c] = tf32r(v.z);
                Kt[(k + 3) * KTLD + c] = tf32r(v.w);
            }
#pragma unroll
            for (int it = 0; it < 16; it++) {
                int idx = tid + it * 128;
                int s = idx >> 5, c4 = (idx & 31) << 2;
                float4 v = *(const float4*)(Vp + (size_t)(s0 + s) * HDIM + c4);
                v.x = tf32r(v.x); v.y = tf32r(v.y); v.z = tf32r(v.z); v.w = tf32r(v.w);
                *(float4*)&Vs[s * VSLD + c4] = v;
            }
        }
        __syncthreads();

        float sa[8][4];
#pragma unroll
        for (int nt = 0; nt < 8; nt++)
#pragma unroll
            for (int e = 0; e < 4; e++) sa[nt][e] = 0.0f;
#pragma unroll
        for (int k8 = 0; k8 < 16; k8++) {
            const int kr0 = (k8 * 8 + (lane & 3)) * KTLD + lr;
            uint32_t bfr[8][2];
#pragma unroll
            for (int nt = 0; nt < 8; nt++) {
                bfr[nt][0] = __float_as_uint(Kt[kr0 + nt * 8]);
                bfr[nt][1] = __float_as_uint(Kt[kr0 + 4 * KTLD + nt * 8]);
            }
#pragma unroll
            for (int nt = 0; nt < 8; nt++) mma_tf32(sa[nt], qf[k8], bfr[nt]);
        }

        float* psrow0 = Ps + (wm + lr) * PSLD + lc;
        float* psrow1 = psrow0 + 8 * PSLD;
#pragma unroll
        for (int nt = 0; nt < 8; nt++) {
            int c = s0 + nt * 8 + lc;
            float p00 = softexp(sa[nt][0], c <= gr0);
            float p01 = softexp(sa[nt][1], c + 1 <= gr0);
            float p10 = softexp(sa[nt][2], c <= gr1);
            float p11 = softexp(sa[nt][3], c + 1 <= gr1);
            ls0 += p00 + p01;
            ls1 += p10 + p11;
            *(float2*)(psrow0 + nt * 8) = make_float2(tf32r(p00), tf32r(p01));
            *(float2*)(psrow1 + nt * 8) = make_float2(tf32r(p10), tf32r(p11));
        }
        __syncthreads();

#pragma unroll
        for (int k8 = 0; k8 < 8; k8++) {
            uint32_t pf[4];
            ldm4(pf, psAddr + (uint32_t)k8 * 32u);
            const int vr0 = (k8 * 8 + (lane & 3)) * VSLD + lr;
#pragma unroll
            for (int nt = 0; nt < 16; nt++) {
                uint32_t bb[2];
                bb[0] = __float_as_uint(Vs[vr0 + nt * 8]);
                bb[1] = __float_as_uint(Vs[vr0 + 4 * VSLD + nt * 8]);
                mma_tf32(o[nt], pf, bb);
            }
        }
        __syncthreads();
    }

    ls0 += __shfl_xor_sync(0xffffffffu, ls0, 1);
    ls0 += __shfl_xor_sync(0xffffffffu, ls0, 2);
    ls1 += __shfl_xor_sync(0xffffffffu, ls1, 1);
    ls1 += __shfl_xor_sync(0xffffffffu, ls1, 2);
    float i0 = 1.0f / ls0, i1 = 1.0f / ls1;
    float* er0 = g_enc + ((size_t)b * TT + gr0) * (NHEADS * HDIM) + n * HDIM + lc;
    float* er1 = g_enc + ((size_t)b * TT + gr1) * (NHEADS * HDIM) + n * HDIM + lc;
#pragma unroll
    for (int nt = 0; nt < 16; nt++) {
        *(float2*)(er0 + nt * 8) =
            make_float2(tf32r(o[nt][0] * i0), tf32r(o[nt][1] * i0));
        *(float2*)(er1 + nt * 8) =
            make_float2(tf32r(o[nt][2] * i1), tf32r(o[nt][3] * i1));
    }
}

// ---------------------------------------------------------------------------
extern "C" void kernel_launch(void* const* d_in, const int* in_sizes, int n_in,
                              void* d_out, int out_size)
{
    const float* x = (const float*)d_in[0];
    const int* positions = (const int*)d_in[1];
    // d_in[2] = attn_mask (causal) — analytic
    const float* w_q = (const float*)d_in[3];
    const float* w_kv = (const float*)d_in[4];
    const float* w_out = (const float*)d_in[5];
    float* out = (float*)d_out;

    float *xr, *wqr, *wkvr, *wor, *qb, *kvb;
    cudaGetSymbolAddress((void**)&xr, g_xr);
    cudaGetSymbolAddress((void**)&wqr, g_wqr);
    cudaGetSymbolAddress((void**)&wkvr, g_wkvr);
    cudaGetSymbolAddress((void**)&wor, g_wor);
    cudaGetSymbolAddress((void**)&qb, g_q);
    cudaGetSymbolAddress((void**)&kvb, g_kv);

    TsTab tt;
    for (int i = 0; i < 64; i++) tt.ts[i] = pow(10000.0, -(double)i / 64.0);

    // prep: tf32-rna round copies (elem counts / 1024 per block)
    round_copy<<<(BB * TT * DD) / 1024, 256>>>(x, xr);
    round_copy<<<(NHEADS * DD * HDIM) / 1024, 256>>>(w_q, wqr);
    round_copy<<<(2 * NKVH * DD * HDIM) / 1024, 256>>>(w_kv, wkvr);
    round_copy<<<(DD * DD) / 1024, 256>>>(w_out, wor);
    rope_table<<<(BB * TT * 64) / 256, 256>>>(positions, tt);

    // merged QKV projection (tf32 mma.sync, cp.async pipeline)
    cudaFuncSetAttribute(proj_merged, cudaFuncAttributeMaxDynamicSharedMemorySize,
                         GSMEM);
    cudaFuncSetAttribute(outproj, cudaFuncAttributeMaxDynamicSharedMemorySize,
                         GSMEM);
    proj_merged<<<dim3(TT / 128, BB * 32), 256, GSMEM>>>();

    rope_apply<<<(BB * NHEADS * TT * 64) / 256, 256>>>(
        qb, NHEADS, NHEADS, 0.08838834764831845f);
    rope_apply<<<(BB * NKVH * TT * 64) / 256, 256>>>(
        kvb, NKVH, 16, 1.0f);

    cudaFuncSetAttribute(attn_kernel, cudaFuncAttributeMaxDynamicSharedMemorySize,
                         SMEM_ATTN);
    attn_kernel<<<dim3(TT / 64, NHEADS, BB), 128, SMEM_ATTN>>>();

    outproj<<<dim3((BB * TT) / 128, DD / 128), 256, GSMEM>>>(out);
}

// round 6
// speedup vs baseline: 4.3524x; 1.0160x over previous
#include <cuda_runtime.h>
#include <math.h>
#include <stdint.h>

#define BB 2
#define TT 2048
#define DD 2048
#define NHEADS 16
#define NKVH 8
#define HDIM 128

// Scratch (allocation-free rule: __device__ globals)
static __device__ float g_q[(size_t)BB * NHEADS * TT * HDIM];   // [b][n][t][h]
static __device__ float g_kv[(size_t)BB * 16 * TT * HDIM];      // [b][j][t][h], j<8=K, j>=8=V
static __device__ float g_enc[(size_t)BB * TT * NHEADS * HDIM]; // [b][t][n*128+h] (tf32-rounded)
static __device__ float2 g_tab[(size_t)BB * TT * 64];           // rope cos/sin
static __device__ float g_xr[(size_t)BB * TT * DD];             // x, tf32-rounded
static __device__ float g_wt[(size_t)4096 * 2048];              // [q;kv] weights^T [nglob][k], tf32
static __device__ float g_wot[(size_t)2048 * 2048];             // w_out^T [n][k], tf32

// ---------------------------------------------------------------------------
// helpers
// ---------------------------------------------------------------------------
__device__ __forceinline__ float tf32r(float x) {
    uint32_t u;
    asm("cvt.rna.tf32.f32 %0, %1;" : "=r"(u) : "f"(x));
    return __uint_as_float(u);
}
__device__ __forceinline__ uint32_t smem_u32(const void* p) {
    return (uint32_t)__cvta_generic_to_shared(p);
}
__device__ __forceinline__ void ldm4(uint32_t* r, uint32_t addr) {
    asm volatile("ldmatrix.sync.aligned.m8n8.x4.shared.b16 {%0,%1,%2,%3}, [%4];"
                 : "=r"(r[0]), "=r"(r[1]), "=r"(r[2]), "=r"(r[3]) : "r"(addr));
}
__device__ __forceinline__ void mma_tf32(float* d, const uint32_t* a, const uint32_t* b) {
    asm volatile(
        "mma.sync.aligned.m16n8k8.row.col.f32.tf32.tf32.f32 "
        "{%0,%1,%2,%3}, {%4,%5,%6,%7}, {%8,%9}, {%0,%1,%2,%3};"
        : "+f"(d[0]), "+f"(d[1]), "+f"(d[2]), "+f"(d[3])
        : "r"(a[0]), "r"(a[1]), "r"(a[2]), "r"(a[3]), "r"(b[0]), "r"(b[1]));
}
__device__ __forceinline__ void cpa16(uint32_t dst, const float* src) {
    asm volatile("cp.async.cg.shared.global [%0], [%1], 16;"
                 :: "r"(dst), "l"(src) : "memory");
}
__device__ __forceinline__ void cpa_commit() {
    asm volatile("cp.async.commit_group;" ::: "memory");
}
template <int N> __device__ __forceinline__ void cpa_wait() {
    asm volatile("cp.async.wait_group %0;" :: "n"(N) : "memory");
}

// ---------------------------------------------------------------------------
// tf32 GEMM: 128x128 tile, BK=16, 4-stage cp.async pipeline, 256 threads
// (8 warps, 4x2), warp tile 32x64, occupancy 2. BOTH operands via ldmatrix.
// A row-major [M,K] (tf32-pre-rounded). Bt row-major [N,K] (tf32-pre-rounded).
// ---------------------------------------------------------------------------
#define TLD 20            // smem row stride (16 k floats + 4 pad)
#define NSTG 4
#define T_STG (128 * TLD) // floats per operand stage
#define GSMEM ((NSTG * 2 * T_STG) * 4)  // 81920 B

__device__ __forceinline__ void gemm_body(
    const float* __restrict__ A,
    const float* __restrict__ Bt,
    float* __restrict__ C, int ldc,
    int K, int m0, int n0)
{
    extern __shared__ float smg[];
    float* As = smg;                  // [NSTG][128][TLD]
    float* Bs = smg + NSTG * T_STG;   // [NSTG][128][TLD]
    const int tid = threadIdx.x;
    const int lane = tid & 31, warp = tid >> 5;
    const int m_warp = (warp & 3) * 32, n_warp = (warp >> 2) * 64;

    // loader mapping: idx = tid (+256); row = idx>>2, k4 = (idx&3)*4
    const int la_row = tid >> 2, la_k4 = (tid & 3) * 4;
    const float* Ap = A + (size_t)(m0 + la_row) * K + la_k4;
    const float* Ap2 = Ap + (size_t)64 * K;
    const float* Bp = Bt + (size_t)(n0 + la_row) * K + la_k4;
    const float* Bp2 = Bp + (size_t)64 * K;
    const uint32_t sm1 = (uint32_t)(la_row * TLD + la_k4) * 4u;
    const uint32_t sm2 = (uint32_t)((la_row + 64) * TLD + la_k4) * 4u;
    const uint32_t aBase = smem_u32(As), bBase = smem_u32(Bs);

    // ldmatrix lane addressing
    const uint32_t aLane =
        (uint32_t)((m_warp + (lane & 15)) * TLD + ((lane & 16) ? 4 : 0)) * 4u;
    const int bRow = (lane & 7) + ((lane >> 4) & 1) * 8;
    const int bCol = ((lane >> 3) & 1) * 4;
    const uint32_t bLane = (uint32_t)((n_warp + bRow) * TLD + bCol) * 4u;

    float acc[2][8][4];
#pragma unroll
    for (int mt = 0; mt < 2; mt++)
#pragma unroll
        for (int nt = 0; nt < 8; nt++)
#pragma unroll
            for (int e = 0; e < 4; e++) acc[mt][nt][e] = 0.0f;

    const int NC = K >> 4;

    // prologue: stages 0..NSTG-2
#pragma unroll
    for (int p = 0; p < NSTG - 1; p++) {
        uint32_t ab = aBase + (uint32_t)(p * T_STG) * 4u;
        uint32_t bb = bBase + (uint32_t)(p * T_STG) * 4u;
        cpa16(ab + sm1, Ap + p * 16);
        cpa16(ab + sm2, Ap2 + p * 16);
        cpa16(bb + sm1, Bp + p * 16);
        cpa16(bb + sm2, Bp2 + p * 16);
        cpa_commit();
    }

    for (int c = 0; c < NC; c++) {
        const int s = c % NSTG;
        cpa_wait<NSTG - 2>();
        __syncthreads();
        const int cn = c + NSTG - 1;
        if (cn < NC) {
            const int sn = cn % NSTG;
            uint32_t ab = aBase + (uint32_t)(sn * T_STG) * 4u;
            uint32_t bb = bBase + (uint32_t)(sn * T_STG) * 4u;
            cpa16(ab + sm1, Ap + cn * 16);
            cpa16(ab + sm2, Ap2 + cn * 16);
            cpa16(bb + sm1, Bp + cn * 16);
            cpa16(bb + sm2, Bp2 + cn * 16);
        }
        cpa_commit();

        const uint32_t aSt = aBase + (uint32_t)(s * T_STG) * 4u + aLane;
        const uint32_t bSt = bBase + (uint32_t)(s * T_STG) * 4u + bLane;
#pragma unroll
        for (int k8 = 0; k8 < 2; k8++) {
            uint32_t af[2][4];
            ldm4(af[0], aSt + (uint32_t)k8 * 32u);
            ldm4(af[1], aSt + (uint32_t)(16 * TLD * 4) + (uint32_t)k8 * 32u);
            uint32_t bt4[4][4];
#pragma unroll
            for (int g = 0; g < 4; g++)
                ldm4(bt4[g], bSt + (uint32_t)(g * 16 * TLD * 4) + (uint32_t)k8 * 32u);
#pragma unroll
            for (int mt = 0; mt < 2; mt++)
#pragma unroll
                for (int g = 0; g < 4; g++) {
                    mma_tf32(acc[mt][2 * g + 0], af[mt], &bt4[g][0]);
                    mma_tf32(acc[mt][2 * g + 1], af[mt], &bt4[g][2]);
                }
        }
    }

    const int r = lane >> 2, cq = (lane & 3) * 2;
#pragma unroll
    for (int mt = 0; mt < 2; mt++) {
        int row = m0 + m_warp + mt * 16 + r;
#pragma unroll
        for (int nt = 0; nt < 8; nt++) {
            int col = n0 + n_warp + nt * 8 + cq;
            *(float2*)&C[(size_t)row * ldc + col] = make_float2(acc[mt][nt][0], acc[mt][nt][1]);
            *(float2*)&C[(size_t)(row + 8) * ldc + col] = make_float2(acc[mt][nt][2], acc[mt][nt][3]);
        }
    }
}

// merged Q+KV projection: bh = b*32 + hh; hh<16 -> Q head, else KV "head"
__global__ __launch_bounds__(256, 2) void proj_merged()
{
    const int bh = blockIdx.y;
    const int b = bh >> 5, hh = bh & 31;
    float* out = (hh < 16)
        ? g_q + ((size_t)(b * NHEADS + hh)) * TT * HDIM
        : g_kv + ((size_t)(b * 16 + (hh - 16))) * TT * HDIM;
    gemm_body(g_xr + (size_t)b * TT * DD,
              g_wt + (size_t)(hh * HDIM) * DD,
              out, HDIM, DD, blockIdx.x * 128, 0);
}

__global__ __launch_bounds__(256, 2) void outproj(float* __restrict__ out)
{
    gemm_body(g_enc, g_wot, out, DD,
              NHEADS * HDIM, blockIdx.x * 128, blockIdx.y * 128);
}

// ---------------------------------------------------------------------------
// prep: tf32 round-copy (x) + rounding transposes (weights -> [N,K])
// ---------------------------------------------------------------------------
__global__ void round_copy(const float* __restrict__ src, float* __restrict__ dst)
{
    int i = blockIdx.x * 256 + threadIdx.x;
    float4 v = ((const float4*)src)[i];
    v.x = tf32r(v.x); v.y = tf32r(v.y); v.z = tf32r(v.z); v.w = tf32r(v.w);
    ((float4*)dst)[i] = v;
}

// out[plane][c][r] = tf32r(in[plane][r][c]); dst row stride 2048
__global__ void transpose_tf32(const float* __restrict__ src, float* __restrict__ dst,
                               int R, int C)
{
    __shared__ float tsm[32][33];
    const int p = blockIdx.z;
    src += (size_t)p * R * C;
    dst += (size_t)p * (size_t)C * 2048;
    int c0 = blockIdx.x * 32, r0 = blockIdx.y * 32;
#pragma unroll
    for (int j = threadIdx.y; j < 32; j += 8)
        tsm[j][threadIdx.x] = src[(size_t)(r0 + j) * C + c0 + threadIdx.x];
    __syncthreads();
#pragma unroll
    for (int j = threadIdx.y; j < 32; j += 8)
        dst[(size_t)(c0 + j) * 2048 + r0 + threadIdx.x] = tf32r(tsm[threadIdx.x][j]);
}

// ---------------------------------------------------------------------------
// RoPE
// ---------------------------------------------------------------------------
struct TsTab { double ts[64]; };

__global__ void rope_table(const int* __restrict__ pos, TsTab tt)
{
    int idx = blockIdx.x * blockDim.x + threadIdx.x;
    int i = idx & 63;
    int t = (idx >> 6) & (TT - 1);
    int b = idx >> 17;
    double th = (double)pos[b * TT + t] * tt.ts[i];
    double sd, cd;
    sincos(th, &sd, &cd);
    g_tab[idx] = make_float2((float)cd, (float)sd);
}

__global__ void rope_apply(float* __restrict__ buf, int nheads, int strideHeads,
                           float scale)
{
    int idx = blockIdx.x * blockDim.x + threadIdx.x;
    int i = idx & 63;
    int t = (idx >> 6) & (TT - 1);
    int rest = idx >> 17;
    int hd = rest % nheads;
    int b = rest / nheads;
    if (b >= BB) return;
    float2 cs = g_tab[((size_t)b * TT + t) * 64 + i];
    size_t base = (((size_t)(b * strideHeads + hd)) * TT + t) * HDIM;
    float f = buf[base + i];
    float se = buf[base + 64 + i];
    buf[base + i] = (f * cs.x - se * cs.y) * scale;
    buf[base + 64 + i] = (se * cs.x + f * cs.y) * scale;
}

// ---------------------------------------------------------------------------
// softcap + static-shift exp, MUFU-free.
// ---------------------------------------------------------------------------
__device__ __forceinline__ float softexp(float x, bool valid) {
    float y = x * 0.02f;
    float u = y * y;
    float pl = fmaf(u, -0.00886324f, 0.02186949f);
    pl = fmaf(u, pl, -0.05396825f);
    pl = fmaf(u, pl, 0.13333333f);
    pl = fmaf(u, pl, -0.33333333f);
    pl = fmaf(u, pl, 1.0f);
    float cap = x * pl;
    if (fabsf(y) > 0.58f) {
        float t = __expf(2.0f * fabsf(y));
        float th = 1.0f - __fdividef(2.0f, t + 1.0f);
        cap = copysignf(50.0f * th, x);
    }
    float t = fmaf(cap, 1.442695041f, -18.755036f);
    float rr = t + 12582912.0f;
    float nf = rr - 12582912.0f;
    float f = t - nf;
    float e = fmaf(f, 1.5403530e-4f, 1.3333558e-3f);
    e = fmaf(f, e, 9.6181291e-3f);
    e = fmaf(f, e, 5.5504109e-2f);
    e = fmaf(f, e, 2.4022651e-1f);
    e = fmaf(f, e, 6.9314718e-1f);
    e = fmaf(f, e, 1.0f);
    int ni = (__float_as_int(rr) & 0x7FFFFF) - 0x400000;
    float sc = __int_as_float((ni + 127) << 23);
    return valid ? e * sc : 0.0f;
}

// ---------------------------------------------------------------------------
// Tensor-core flash attention (mma.sync tf32). g_enc stores tf32-rounded.
// ---------------------------------------------------------------------------
#define KTLD 72
#define VSLD 136
#define PSLD 68
#define QSLD 132
#define SMEM_ATTN ((128 * KTLD + 64 * VSLD + 64 * PSLD) * 4)

__global__ __launch_bounds__(128, 2) void attn_kernel()
{
    extern __shared__ float sm[];
    float* Kt = sm;
    float* Vs = sm + 128 * KTLD;
    float* Ps = Vs + 64 * VSLD;
    float* Qs = sm;

    const int tid = threadIdx.x;
    const int lane = tid & 31, warp = tid >> 5;
    const int wm = warp * 16;
    const int lr = lane >> 2, lc = (lane & 3) * 2;
    const int qi = gridDim.x - 1 - blockIdx.x;
    const int q0 = qi * 64;
    const int n = blockIdx.y, b = blockIdx.z;
    const int kvh = n >> 1;
    const float* Qp = g_q + ((size_t)(b * NHEADS + n)) * TT * HDIM;
    const float* Kp = g_kv + ((size_t)(b * 16 + kvh)) * TT * HDIM;
    const float* Vp = g_kv + ((size_t)(b * 16 + 8 + kvh)) * TT * HDIM;

    {
        int c = tid & 63, k4 = (tid >> 6) << 2;
#pragma unroll
        for (int kb = 0; kb < 16; kb++) {
            int k = kb * 8 + k4;
            float4 v = *(const float4*)(Qp + (size_t)(q0 + c) * HDIM + k);
            v.x = tf32r(v.x); v.y = tf32r(v.y); v.z = tf32r(v.z); v.w = tf32r(v.w);
            *(float4*)&Qs[c * QSLD + k] = v;
        }
    }
    __syncthreads();
    uint32_t qf[16][4];
    {
        uint32_t baseQ = smem_u32(Qs);
        int r = lane & 15, cA = (lane & 16) ? 4 : 0;
        uint32_t addr = baseQ + (uint32_t)((wm + r) * QSLD + cA) * 4u;
#pragma unroll
        for (int k8 = 0; k8 < 16; k8++) ldm4(qf[k8], addr + (uint32_t)k8 * 32u);
    }
    __syncthreads();

    float o[16][4];
#pragma unroll
    for (int nt = 0; nt < 16; nt++)
#pragma unroll
        for (int e = 0; e < 4; e++) o[nt][e] = 0.0f;
    float ls0 = 0.0f, ls1 = 0.0f;

    const int gr0 = q0 + wm + lr;
    const int gr1 = gr0 + 8;
    const uint32_t psAddr = smem_u32(Ps) +
        (uint32_t)(((wm + (lane & 15)) * PSLD + ((lane >> 4) << 2)) * 4);

    for (int tile = 0; tile <= qi; tile++) {
        const int s0 = tile * 64;
        {
            int c = tid & 63, k4 = (tid >> 6) << 2;
#pragma unroll
            for (int kb = 0; kb < 16; kb++) {
                int k = kb * 8 + k4;
                float4 v = *(const float4*)(Kp + (size_t)(s0 + c) * HDIM + k);
                Kt[(k + 0) * KTLD + c] = tf32r(v.x);
                Kt[(k + 1) * KTLD + c] = tf32r(v.y);
                Kt[(k + 2) * KTLD + c] = tf32r(v.z);
                Kt[(k + 3) * KTLD + c] = tf32r(v.w);
            }
#pragma unroll
            for (int it = 0; it < 16; it++) {
                int idx = tid + it * 128;
                int s = idx >> 5, c4 = (idx & 31) << 2;
                float4 v = *(const float4*)(Vp + (size_t)(s0 + s) * HDIM + c4);
                v.x = tf32r(v.x); v.y = tf32r(v.y); v.z = tf32r(v.z); v.w = tf32r(v.w);
                *(float4*)&Vs[s * VSLD + c4] = v;
            }
        }
        __syncthreads();

        float sa[8][4];
#pragma unroll
        for (int nt = 0; nt < 8; nt++)
#pragma unroll
            for (int e = 0; e < 4; e++) sa[nt][e] = 0.0f;
#pragma unroll
        for (int k8 = 0; k8 < 16; k8++) {
            const int kr0 = (k8 * 8 + (lane & 3)) * KTLD + lr;
            uint32_t bfr[8][2];
#pragma unroll
            for (int nt = 0; nt < 8; nt++) {
                bfr[nt][0] = __float_as_uint(Kt[kr0 + nt * 8]);
                bfr[nt][1] = __float_as_uint(Kt[kr0 + 4 * KTLD + nt * 8]);
            }
#pragma unroll
            for (int nt = 0; nt < 8; nt++) mma_tf32(sa[nt], qf[k8], bfr[nt]);
        }

        float* psrow0 = Ps + (wm + lr) * PSLD + lc;
        float* psrow1 = psrow0 + 8 * PSLD;
#pragma unroll
        for (int nt = 0; nt < 8; nt++) {
            int c = s0 + nt * 8 + lc;
            float p00 = softexp(sa[nt][0], c <= gr0);
            float p01 = softexp(sa[nt][1], c + 1 <= gr0);
            float p10 = softexp(sa[nt][2], c <= gr1);
            float p11 = softexp(sa[nt][3], c + 1 <= gr1);
            ls0 += p00 + p01;
            ls1 += p10 + p11;
            *(float2*)(psrow0 + nt * 8) = make_float2(tf32r(p00), tf32r(p01));
            *(float2*)(psrow1 + nt * 8) = make_float2(tf32r(p10), tf32r(p11));
        }
        __syncthreads();

#pragma unroll
        for (int k8 = 0; k8 < 8; k8++) {
            uint32_t pf[4];
            ldm4(pf, psAddr + (uint32_t)k8 * 32u);
            const int vr0 = (k8 * 8 + (lane & 3)) * VSLD + lr;
#pragma unroll
            for (int nt = 0; nt < 16; nt++) {
                uint32_t bb[2];
                bb[0] = __float_as_uint(Vs[vr0 + nt * 8]);
                bb[1] = __float_as_uint(Vs[vr0 + 4 * VSLD + nt * 8]);
                mma_tf32(o[nt], pf, bb);
            }
        }
        __syncthreads();
    }

    ls0 += __shfl_xor_sync(0xffffffffu, ls0, 1);
    ls0 += __shfl_xor_sync(0xffffffffu, ls0, 2);
    ls1 += __shfl_xor_sync(0xffffffffu, ls1, 1);
    ls1 += __shfl_xor_sync(0xffffffffu, ls1, 2);
    float i0 = 1.0f / ls0, i1 = 1.0f / ls1;
    float* er0 = g_enc + ((size_t)b * TT + gr0) * (NHEADS * HDIM) + n * HDIM + lc;
    float* er1 = g_enc + ((size_t)b * TT + gr1) * (NHEADS * HDIM) + n * HDIM + lc;
#pragma unroll
    for (int nt = 0; nt < 16; nt++) {
        *(float2*)(er0 + nt * 8) =
            make_float2(tf32r(o[nt][0] * i0), tf32r(o[nt][1] * i0));
        *(float2*)(er1 + nt * 8) =
            make_float2(tf32r(o[nt][2] * i1), tf32r(o[nt][3] * i1));
    }
}

// ---------------------------------------------------------------------------
extern "C" void kernel_launch(void* const* d_in, const int* in_sizes, int n_in,
                              void* d_out, int out_size)
{
    const float* x = (const float*)d_in[0];
    const int* positions = (const int*)d_in[1];
    // d_in[2] = attn_mask (causal) — analytic
    const float* w_q = (const float*)d_in[3];
    const float* w_kv = (const float*)d_in[4];
    const float* w_out = (const float*)d_in[5];
    float* out = (float*)d_out;

    float *xr, *wt, *wot, *qb, *kvb;
    cudaGetSymbolAddress((void**)&xr, g_xr);
    cudaGetSymbolAddress((void**)&wt, g_wt);
    cudaGetSymbolAddress((void**)&wot, g_wot);
    cudaGetSymbolAddress((void**)&qb, g_q);
    cudaGetSymbolAddress((void**)&kvb, g_kv);

    TsTab tt;
    for (int i = 0; i < 64; i++) tt.ts[i] = pow(10000.0, -(double)i / 64.0);

    // prep
    round_copy<<<(BB * TT * DD) / 1024, 256>>>(x, xr);
    transpose_tf32<<<dim3(4, 64, 16), dim3(32, 8)>>>(w_q, wt, 2048, 128);
    transpose_tf32<<<dim3(4, 64, 16), dim3(32, 8)>>>(
        w_kv, wt + (size_t)2048 * 2048, 2048, 128);
    transpose_tf32<<<dim3(64, 64, 1), dim3(32, 8)>>>(w_out, wot, 2048, 2048);
    rope_table<<<(BB * TT * 64) / 256, 256>>>(positions, tt);

    // merged QKV projection
    cudaFuncSetAttribute(proj_merged, cudaFuncAttributeMaxDynamicSharedMemorySize,
                         GSMEM);
    cudaFuncSetAttribute(outproj, cudaFuncAttributeMaxDynamicSharedMemorySize,
                         GSMEM);
    proj_merged<<<dim3(TT / 128, BB * 32), 256, GSMEM>>>();

    rope_apply<<<(BB * NHEADS * TT * 64) / 256, 256>>>(
        qb, NHEADS, NHEADS, 0.08838834764831845f);
    rope_apply<<<(BB * NKVH * TT * 64) / 256, 256>>>(
        kvb, NKVH, 16, 1.0f);

    cudaFuncSetAttribute(attn_kernel, cudaFuncAttributeMaxDynamicSharedMemorySize,
                         SMEM_ATTN);
    attn_kernel<<<dim3(TT / 64, NHEADS, BB), 128, SMEM_ATTN>>>();

    outproj<<<dim3((BB * TT) / 128, DD / 128), 256, GSMEM>>>(out);
}